// round 1
// baseline (speedup 1.0000x reference)
#include <cuda_runtime.h>
#include <math.h>

#define F_IN 34
#define HID 256
#define NHEAD 8
#define HD 32
#define NLAYER 5
#define NMAX 50000
#define EMAX 800000
#define GMAX 2000

// ---------------- scratch (static __device__, no allocation) ----------------
__device__ float g_h[NMAX * HID];
__device__ float g_a[NMAX * HID];
__device__ float g_b[NMAX * HID];
__device__ float g_c[NMAX * HID];
__device__ float g_t[NMAX * HID];
__device__ float g_pool_sum[GMAX * HID];
__device__ float g_pool_max[GMAX * HID];
__device__ float g_cnt[GMAX];
__device__ float g_ge[GMAX * 2 * HID];
__device__ int g_deg[NMAX];
__device__ int g_rowptr[NMAX + 1];
__device__ int g_wptr[NMAX];
__device__ int g_csrc[EMAX];

// ---------------- helpers ----------------
__device__ __forceinline__ float gelu_f(float x) {
    return 0.5f * x * (1.0f + erff(x * 0.7071067811865475f));
}

__device__ __forceinline__ void atomicMaxFloat(float* addr, float value) {
    if (value >= 0.0f)
        atomicMax((int*)addr, __float_as_int(value));
    else
        atomicMin((unsigned int*)addr, __float_as_uint(value));
}

// ---------------- init ----------------
__global__ void init_kernel(int N, int G) {
    int i = blockIdx.x * blockDim.x + threadIdx.x;
    if (i < G * HID) {
        g_pool_sum[i] = 0.0f;
        g_pool_max[i] = -INFINITY;
    }
    if (i < G) g_cnt[i] = 0.0f;
    if (i < N) g_deg[i] = 0;
}

// ---------------- CSR build ----------------
__global__ void deg_kernel(const int* __restrict__ dst, int E) {
    int e = blockIdx.x * blockDim.x + threadIdx.x;
    if (e < E) atomicAdd(&g_deg[dst[e]], 1);
}

// one-block exclusive scan over N elements -> g_rowptr, g_wptr
__global__ void scan_kernel(int N) {
    __shared__ int sdata[1024];
    __shared__ int carry;
    if (threadIdx.x == 0) carry = 0;
    __syncthreads();
    for (int base = 0; base < N; base += 1024) {
        int i = base + threadIdx.x;
        int v = (i < N) ? g_deg[i] : 0;
        sdata[threadIdx.x] = v;
        __syncthreads();
        for (int off = 1; off < 1024; off <<= 1) {
            int t = (threadIdx.x >= off) ? sdata[threadIdx.x - off] : 0;
            __syncthreads();
            sdata[threadIdx.x] += t;
            __syncthreads();
        }
        int incl = sdata[threadIdx.x];
        int excl = incl - v;
        if (i < N) {
            g_rowptr[i] = carry + excl;
            g_wptr[i] = carry + excl;
        }
        __syncthreads();
        if (threadIdx.x == 1023) carry += sdata[1023];
        __syncthreads();
    }
    if (threadIdx.x == 0) g_rowptr[N] = carry;
}

__global__ void scatter_kernel(const int* __restrict__ src, const int* __restrict__ dst, int E) {
    int e = blockIdx.x * blockDim.x + threadIdx.x;
    if (e >= E) return;
    int d = dst[e];
    int pos = atomicAdd(&g_wptr[d], 1);
    g_csrc[pos] = src[e];
}

// ---------------- SGEMM: C[M,Nc] = A[M,K] @ B[K,Nc] + bias ----------------
#define BM 64
#define BN 64
#define BK 16
__global__ void gemm_bias_kernel(const float* __restrict__ A, const float* __restrict__ B,
                                 const float* __restrict__ bias, float* __restrict__ C,
                                 int M, int K, int Nc) {
    __shared__ float As[BK][BM + 1];
    __shared__ float Bs[BK][BN];
    int tid = threadIdx.x;  // 256
    int tx = tid & 15, ty = tid >> 4;
    int rowBase = blockIdx.y * BM;
    int colBase = blockIdx.x * BN;
    float acc[4][4];
#pragma unroll
    for (int i = 0; i < 4; i++)
#pragma unroll
        for (int j = 0; j < 4; j++) acc[i][j] = 0.0f;

    for (int k0 = 0; k0 < K; k0 += BK) {
#pragma unroll
        for (int it = 0; it < 4; it++) {
            int e = tid + it * 256;
            int kk = e % BK, mm = e / BK;
            int r = rowBase + mm, kz = k0 + kk;
            As[kk][mm] = (r < M && kz < K) ? A[(size_t)r * K + kz] : 0.0f;
        }
#pragma unroll
        for (int it = 0; it < 4; it++) {
            int e = tid + it * 256;
            int nn = e % BN, kk = e / BN;
            int kz = k0 + kk, cc = colBase + nn;
            Bs[kk][nn] = (kz < K && cc < Nc) ? B[(size_t)kz * Nc + cc] : 0.0f;
        }
        __syncthreads();
#pragma unroll
        for (int kk = 0; kk < BK; kk++) {
            float a[4], b[4];
#pragma unroll
            for (int i = 0; i < 4; i++) a[i] = As[kk][ty * 4 + i];
#pragma unroll
            for (int j = 0; j < 4; j++) b[j] = Bs[kk][tx * 4 + j];
#pragma unroll
            for (int i = 0; i < 4; i++)
#pragma unroll
                for (int j = 0; j < 4; j++) acc[i][j] += a[i] * b[j];
        }
        __syncthreads();
    }
#pragma unroll
    for (int i = 0; i < 4; i++) {
        int r = rowBase + ty * 4 + i;
        if (r >= M) continue;
#pragma unroll
        for (int j = 0; j < 4; j++) {
            int cc = colBase + tx * 4 + j;
            if (cc < Nc) C[(size_t)r * Nc + cc] = acc[i][j] + bias[cc];
        }
    }
}

// ---------------- LayerNorm (+ optional GELU), one block per row ----------------
template <int DIM, bool ACT>
__global__ void ln_kernel(const float* __restrict__ in, const float* __restrict__ g,
                          const float* __restrict__ b, float* __restrict__ out) {
    int n = blockIdx.x, c = threadIdx.x;
    float v = in[n * DIM + c];
    __shared__ float sh[DIM];
    sh[c] = v;
    __syncthreads();
    for (int off = DIM / 2; off > 0; off >>= 1) {
        if (c < off) sh[c] += sh[c + off];
        __syncthreads();
    }
    float mean = sh[0] * (1.0f / DIM);
    __syncthreads();
    float d = v - mean;
    sh[c] = d * d;
    __syncthreads();
    for (int off = DIM / 2; off > 0; off >>= 1) {
        if (c < off) sh[c] += sh[c + off];
        __syncthreads();
    }
    float var = sh[0] * (1.0f / DIM);
    float y = d * rsqrtf(var + 1e-5f) * g[c] + b[c];
    if (ACT) y = gelu_f(y);
    out[n * DIM + c] = y;
}

// ---------------- GATv2 layer: per-node online-softmax aggregation, fused LN+GELU+residual ----------------
__global__ void gat_kernel(const float* __restrict__ xl, const float* __restrict__ xr,
                           const float* __restrict__ att, const float* __restrict__ bias,
                           const float* __restrict__ lng, const float* __restrict__ lnb,
                           float* __restrict__ h) {
    int n = blockIdx.x;
    int c = threadIdx.x;  // 0..255 ; head = c/32, dim = c%32
    float xr_c = xr[n * HID + c];
    float att_c = att[c];
    float m = -INFINITY, den = 0.0f, acc = 0.0f;
    int beg = g_rowptr[n], end = g_rowptr[n + 1];
    for (int j = beg; j <= end; j++) {  // j==end -> self loop
        int s = (j < end) ? g_csrc[j] : n;
        float xlc = xl[s * HID + c];
        float t = xlc + xr_c;
        t = (t > 0.0f) ? t : 0.2f * t;  // leaky_relu 0.2
        float p = t * att_c;
#pragma unroll
        for (int o = 16; o > 0; o >>= 1) p += __shfl_xor_sync(0xffffffffu, p, o);
        float mn = fmaxf(m, p);
        float sc = __expf(m - mn);
        float w = __expf(p - mn);
        acc = acc * sc + w * xlc;
        den = den * sc + w;
        m = mn;
    }
    float out = acc / (den + 1e-16f) + bias[c];
    // fused LN + GELU + residual
    __shared__ float sh[HID];
    sh[c] = out;
    __syncthreads();
    for (int off = HID / 2; off > 0; off >>= 1) {
        if (c < off) sh[c] += sh[c + off];
        __syncthreads();
    }
    float mean = sh[0] * (1.0f / HID);
    __syncthreads();
    float d = out - mean;
    sh[c] = d * d;
    __syncthreads();
    for (int off = HID / 2; off > 0; off >>= 1) {
        if (c < off) sh[c] += sh[c + off];
        __syncthreads();
    }
    float var = sh[0] * (1.0f / HID);
    float y = d * rsqrtf(var + 1e-5f) * lng[c] + lnb[c];
    h[n * HID + c] += gelu_f(y);
}

// ---------------- TransformerConv: per-node online-softmax attention, fused LN+residual ----------------
__global__ void trans_kernel(const float* __restrict__ q, const float* __restrict__ k,
                             const float* __restrict__ v, const float* __restrict__ skip,
                             const float* __restrict__ lng, const float* __restrict__ lnb,
                             float* __restrict__ h) {
    int n = blockIdx.x;
    int c = threadIdx.x;
    const float scale = 0.17677669529663687f;  // 1/sqrt(32)
    float q_c = q[n * HID + c];
    float m = -INFINITY, den = 0.0f, acc = 0.0f;
    int beg = g_rowptr[n], end = g_rowptr[n + 1];
    for (int j = beg; j < end; j++) {  // no self loops
        int s = g_csrc[j];
        float kc = k[s * HID + c];
        float p = q_c * kc;
#pragma unroll
        for (int o = 16; o > 0; o >>= 1) p += __shfl_xor_sync(0xffffffffu, p, o);
        p *= scale;
        float vc = v[s * HID + c];
        float mn = fmaxf(m, p);
        float sc = __expf(m - mn);
        float w = __expf(p - mn);
        acc = acc * sc + w * vc;
        den = den * sc + w;
        m = mn;
    }
    float out = acc / (den + 1e-16f) + skip[n * HID + c];
    // fused LN + residual (no GELU)
    __shared__ float sh[HID];
    sh[c] = out;
    __syncthreads();
    for (int off = HID / 2; off > 0; off >>= 1) {
        if (c < off) sh[c] += sh[c + off];
        __syncthreads();
    }
    float mean = sh[0] * (1.0f / HID);
    __syncthreads();
    float d = out - mean;
    sh[c] = d * d;
    __syncthreads();
    for (int off = HID / 2; off > 0; off >>= 1) {
        if (c < off) sh[c] += sh[c + off];
        __syncthreads();
    }
    float var = sh[0] * (1.0f / HID);
    float y = d * rsqrtf(var + 1e-5f) * lng[c] + lnb[c];
    h[n * HID + c] += y;
}

// ---------------- pooling ----------------
__global__ void pool_kernel(const float* __restrict__ h, const int* __restrict__ batch) {
    int n = blockIdx.x, c = threadIdx.x;
    int g = batch[n];
    float v = h[n * HID + c];
    atomicAdd(&g_pool_sum[g * HID + c], v);
    atomicMaxFloat(&g_pool_max[g * HID + c], v);
    if (c == 0) atomicAdd(&g_cnt[g], 1.0f);
}

__global__ void finalize_kernel(int G) {
    int i = blockIdx.x * blockDim.x + threadIdx.x;
    if (i >= G * 2 * HID) return;
    int g = i / (2 * HID), c = i % (2 * HID);
    float v;
    if (c < HID) {
        v = g_pool_sum[g * HID + c] / fmaxf(g_cnt[g], 1.0f);
    } else {
        v = g_pool_max[g * HID + (c - HID)];
        if (!isfinite(v)) v = 0.0f;
    }
    g_ge[i] = v;
}

// ---------------- launch ----------------
static void run_gemm(const float* A, const float* B, const float* bias, float* C,
                     int M, int K, int Nc) {
    dim3 grid((Nc + BN - 1) / BN, (M + BM - 1) / BM);
    gemm_bias_kernel<<<grid, 256>>>(A, B, bias, C, M, K, Nc);
}

extern "C" void kernel_launch(void* const* d_in, const int* in_sizes, int n_in,
                              void* d_out, int out_size) {
    const float* x = (const float*)d_in[0];
    const int* ei = (const int*)d_in[1];
    const int* batch = (const int*)d_in[2];
    const float* in_W = (const float*)d_in[3];
    const float* in_b = (const float*)d_in[4];
    const float* in_ln_g = (const float*)d_in[5];
    const float* in_ln_b = (const float*)d_in[6];
    const float* gat_Wl = (const float*)d_in[7];
    const float* gat_bl = (const float*)d_in[8];
    const float* gat_Wr = (const float*)d_in[9];
    const float* gat_br = (const float*)d_in[10];
    const float* gat_att = (const float*)d_in[11];
    const float* gat_bias = (const float*)d_in[12];
    const float* gat_ln_g = (const float*)d_in[13];
    const float* gat_ln_b = (const float*)d_in[14];
    const float* tr_Wq = (const float*)d_in[15];
    const float* tr_bq = (const float*)d_in[16];
    const float* tr_Wk = (const float*)d_in[17];
    const float* tr_bk = (const float*)d_in[18];
    const float* tr_Wv = (const float*)d_in[19];
    const float* tr_bv = (const float*)d_in[20];
    const float* tr_Wskip = (const float*)d_in[21];
    const float* tr_bskip = (const float*)d_in[22];
    const float* tr_ln_g = (const float*)d_in[23];
    const float* tr_ln_b = (const float*)d_in[24];
    const float* out_W = (const float*)d_in[25];
    const float* out_b = (const float*)d_in[26];
    const float* out_ln_g = (const float*)d_in[27];
    const float* out_ln_b = (const float*)d_in[28];

    int N = in_sizes[0] / F_IN;
    int E = in_sizes[1] / 2;
    int G = out_size / (2 * HID);
    const int* src = ei;
    const int* dst = ei + E;

    float *hP, *aP, *bP, *cP, *tP, *geP;
    cudaGetSymbolAddress((void**)&hP, g_h);
    cudaGetSymbolAddress((void**)&aP, g_a);
    cudaGetSymbolAddress((void**)&bP, g_b);
    cudaGetSymbolAddress((void**)&cP, g_c);
    cudaGetSymbolAddress((void**)&tP, g_t);
    cudaGetSymbolAddress((void**)&geP, g_ge);

    // init pool/deg
    int initN = (G * HID > N) ? G * HID : N;
    init_kernel<<<(initN + 255) / 256, 256>>>(N, G);

    // input embed: h = gelu(LN(x @ in_W + in_b))
    run_gemm(x, in_W, in_b, tP, N, F_IN, HID);
    ln_kernel<HID, true><<<N, HID>>>(tP, in_ln_g, in_ln_b, hP);

    // build CSR by destination
    deg_kernel<<<(E + 255) / 256, 256>>>(dst, E);
    scan_kernel<<<1, 1024>>>(N);
    scatter_kernel<<<(E + 255) / 256, 256>>>(src, dst, E);

    // 5 GATv2 layers
    for (int l = 0; l < NLAYER; l++) {
        run_gemm(hP, gat_Wl + (size_t)l * HID * HID, gat_bl + (size_t)l * HID, aP, N, HID, HID);
        run_gemm(hP, gat_Wr + (size_t)l * HID * HID, gat_br + (size_t)l * HID, bP, N, HID, HID);
        gat_kernel<<<N, HID>>>(aP, bP, gat_att + (size_t)l * HID, gat_bias + (size_t)l * HID,
                               gat_ln_g + (size_t)l * HID, gat_ln_b + (size_t)l * HID, hP);
    }

    // TransformerConv
    run_gemm(hP, tr_Wq, tr_bq, aP, N, HID, HID);
    run_gemm(hP, tr_Wk, tr_bk, bP, N, HID, HID);
    run_gemm(hP, tr_Wv, tr_bv, cP, N, HID, HID);
    run_gemm(hP, tr_Wskip, tr_bskip, tP, N, HID, HID);
    trans_kernel<<<N, HID>>>(aP, bP, cP, tP, tr_ln_g, tr_ln_b, hP);

    // pooling
    pool_kernel<<<N, HID>>>(hP, batch);
    finalize_kernel<<<(G * 2 * HID + 255) / 256, 256>>>(G);

    // output projection + LN + GELU
    run_gemm(geP, out_W, out_b, bP, G, 2 * HID, 2 * HID);
    ln_kernel<2 * HID, true><<<G, 2 * HID>>>(bP, out_ln_g, out_ln_b, (float*)d_out);
}

// round 2
// speedup vs baseline: 1.5513x; 1.5513x over previous
#include <cuda_runtime.h>
#include <math.h>

#define F_IN 34
#define HID 256
#define NHEAD 8
#define HD 32
#define NLAYER 5
#define NMAX 50000
#define EMAX 800000
#define GMAX 2000

// ---------------- scratch (static __device__, no allocation) ----------------
__device__ float g_h[NMAX * HID];
__device__ float g_a[NMAX * HID];
__device__ float g_b[NMAX * HID];
__device__ float g_c[NMAX * HID];
__device__ float g_t[NMAX * HID];
__device__ float g_pool_sum[GMAX * HID];
__device__ float g_pool_max[GMAX * HID];
__device__ float g_cnt[GMAX];
__device__ float g_ge[GMAX * 2 * HID];
__device__ int g_deg[NMAX];
__device__ int g_rowptr[NMAX + 1];
__device__ int g_wptr[NMAX];
__device__ int g_csrc[EMAX];

// ---------------- helpers ----------------
__device__ __forceinline__ float gelu_f(float x) {
    return 0.5f * x * (1.0f + erff(x * 0.7071067811865475f));
}

__device__ __forceinline__ void atomicMaxFloat(float* addr, float value) {
    if (value >= 0.0f)
        atomicMax((int*)addr, __float_as_int(value));
    else
        atomicMin((unsigned int*)addr, __float_as_uint(value));
}

__device__ __forceinline__ unsigned f2tf32(float x) {
    unsigned r;
    asm("cvt.rna.tf32.f32 %0, %1;" : "=r"(r) : "f"(x));
    return r;
}

__device__ __forceinline__ void mma_tf32(float c[4], const unsigned a[4], unsigned b0, unsigned b1) {
    asm volatile(
        "mma.sync.aligned.m16n8k8.row.col.f32.tf32.tf32.f32 "
        "{%0,%1,%2,%3}, {%4,%5,%6,%7}, {%8,%9}, {%0,%1,%2,%3};"
        : "+f"(c[0]), "+f"(c[1]), "+f"(c[2]), "+f"(c[3])
        : "r"(a[0]), "r"(a[1]), "r"(a[2]), "r"(a[3]), "r"(b0), "r"(b1));
}

// ---------------- init ----------------
__global__ void init_kernel(int N, int G) {
    int i = blockIdx.x * blockDim.x + threadIdx.x;
    if (i < G * HID) {
        g_pool_sum[i] = 0.0f;
        g_pool_max[i] = -INFINITY;
    }
    if (i < G) g_cnt[i] = 0.0f;
    if (i < N) g_deg[i] = 0;
}

// ---------------- CSR build ----------------
__global__ void deg_kernel(const int* __restrict__ dst, int E) {
    int e = blockIdx.x * blockDim.x + threadIdx.x;
    if (e < E) atomicAdd(&g_deg[dst[e]], 1);
}

__global__ void scan_kernel(int N) {
    __shared__ int sdata[1024];
    __shared__ int carry;
    if (threadIdx.x == 0) carry = 0;
    __syncthreads();
    for (int base = 0; base < N; base += 1024) {
        int i = base + threadIdx.x;
        int v = (i < N) ? g_deg[i] : 0;
        sdata[threadIdx.x] = v;
        __syncthreads();
        for (int off = 1; off < 1024; off <<= 1) {
            int t = (threadIdx.x >= off) ? sdata[threadIdx.x - off] : 0;
            __syncthreads();
            sdata[threadIdx.x] += t;
            __syncthreads();
        }
        int incl = sdata[threadIdx.x];
        int excl = incl - v;
        if (i < N) {
            g_rowptr[i] = carry + excl;
            g_wptr[i] = carry + excl;
        }
        __syncthreads();
        if (threadIdx.x == 1023) carry += sdata[1023];
        __syncthreads();
    }
    if (threadIdx.x == 0) g_rowptr[N] = carry;
}

__global__ void scatter_kernel(const int* __restrict__ src, const int* __restrict__ dst, int E) {
    int e = blockIdx.x * blockDim.x + threadIdx.x;
    if (e >= E) return;
    int d = dst[e];
    int pos = atomicAdd(&g_wptr[d], 1);
    g_csrc[pos] = src[e];
}

// ---------------- fp32 SGEMM (small / precision-critical GEMMs) ----------------
#define BM 64
#define BN 64
#define BK 16
__global__ void gemm_bias_kernel(const float* __restrict__ A, const float* __restrict__ B,
                                 const float* __restrict__ bias, float* __restrict__ C,
                                 int M, int K, int Nc) {
    __shared__ float As[BK][BM + 1];
    __shared__ float Bs[BK][BN];
    int tid = threadIdx.x;
    int tx = tid & 15, ty = tid >> 4;
    int rowBase = blockIdx.y * BM;
    int colBase = blockIdx.x * BN;
    float acc[4][4];
#pragma unroll
    for (int i = 0; i < 4; i++)
#pragma unroll
        for (int j = 0; j < 4; j++) acc[i][j] = 0.0f;

    for (int k0 = 0; k0 < K; k0 += BK) {
#pragma unroll
        for (int it = 0; it < 4; it++) {
            int e = tid + it * 256;
            int kk = e % BK, mm = e / BK;
            int r = rowBase + mm, kz = k0 + kk;
            As[kk][mm] = (r < M && kz < K) ? A[(size_t)r * K + kz] : 0.0f;
        }
#pragma unroll
        for (int it = 0; it < 4; it++) {
            int e = tid + it * 256;
            int nn = e % BN, kk = e / BN;
            int kz = k0 + kk, cc = colBase + nn;
            Bs[kk][nn] = (kz < K && cc < Nc) ? B[(size_t)kz * Nc + cc] : 0.0f;
        }
        __syncthreads();
#pragma unroll
        for (int kk = 0; kk < BK; kk++) {
            float a[4], b[4];
#pragma unroll
            for (int i = 0; i < 4; i++) a[i] = As[kk][ty * 4 + i];
#pragma unroll
            for (int j = 0; j < 4; j++) b[j] = Bs[kk][tx * 4 + j];
#pragma unroll
            for (int i = 0; i < 4; i++)
#pragma unroll
                for (int j = 0; j < 4; j++) acc[i][j] += a[i] * b[j];
        }
        __syncthreads();
    }
#pragma unroll
    for (int i = 0; i < 4; i++) {
        int r = rowBase + ty * 4 + i;
        if (r >= M) continue;
#pragma unroll
        for (int j = 0; j < 4; j++) {
            int cc = colBase + tx * 4 + j;
            if (cc < Nc) C[(size_t)r * Nc + cc] = acc[i][j] + bias[cc];
        }
    }
}

// ---------------- tf32 tensor-core GEMM ----------------
// C[M,Nc] = A[M,K] @ B[K,Nc] + bias.  Requires Nc % 128 == 0, K % 16 == 0.
#define TBM 128
#define TBN 128
#define TBK 16
#define TPAD 4
__global__ __launch_bounds__(256, 2) void gemm_tf32_kernel(
    const float* __restrict__ A, const float* __restrict__ B,
    const float* __restrict__ bias, float* __restrict__ C,
    int M, int K, int Nc) {
    __shared__ unsigned As[TBK][TBM + TPAD];  // transposed: [k][m]
    __shared__ unsigned Bs[TBK][TBN + TPAD];  // [k][n]

    int tid = threadIdx.x;
    int lane = tid & 31;
    int warp = tid >> 5;
    int warp_m = warp & 3;  // 4 warp rows x 32
    int warp_n = warp >> 2; // 2 warp cols x 64
    int rowBase = blockIdx.y * TBM;
    int colBase = blockIdx.x * TBN;

    float acc[2][8][4];
#pragma unroll
    for (int mt = 0; mt < 2; mt++)
#pragma unroll
        for (int nt = 0; nt < 8; nt++)
#pragma unroll
            for (int i = 0; i < 4; i++) acc[mt][nt][i] = 0.0f;

    // staging registers for global->smem pipeline
    float4 ar[2], br[2];
    int kIters = K / TBK;

    // A load: thread t covers row=t/4, k-quad=t%4 (float4 along K)
    // B load: thread t covers k=t/32, n-quad=t%32 (float4 along N)
    auto load_g = [&](int it) {
        int k0 = it * TBK;
#pragma unroll
        for (int i = 0; i < 2; i++) {
            int t = tid + i * 256;
            int r = t >> 2, kq = t & 3;
            int gr = rowBase + r;
            if (gr < M)
                ar[i] = *(const float4*)(A + (size_t)gr * K + k0 + kq * 4);
            else
                ar[i] = make_float4(0.f, 0.f, 0.f, 0.f);
        }
#pragma unroll
        for (int i = 0; i < 2; i++) {
            int t = tid + i * 256;
            int kk = t >> 5, n4 = t & 31;
            br[i] = *(const float4*)(B + (size_t)(k0 + kk) * Nc + colBase + n4 * 4);
        }
    };
    auto store_s = [&]() {
#pragma unroll
        for (int i = 0; i < 2; i++) {
            int t = tid + i * 256;
            int r = t >> 2, kq = t & 3;
            As[kq * 4 + 0][r] = f2tf32(ar[i].x);
            As[kq * 4 + 1][r] = f2tf32(ar[i].y);
            As[kq * 4 + 2][r] = f2tf32(ar[i].z);
            As[kq * 4 + 3][r] = f2tf32(ar[i].w);
        }
#pragma unroll
        for (int i = 0; i < 2; i++) {
            int t = tid + i * 256;
            int kk = t >> 5, n4 = t & 31;
            Bs[kk][n4 * 4 + 0] = f2tf32(br[i].x);
            Bs[kk][n4 * 4 + 1] = f2tf32(br[i].y);
            Bs[kk][n4 * 4 + 2] = f2tf32(br[i].z);
            Bs[kk][n4 * 4 + 3] = f2tf32(br[i].w);
        }
    };

    load_g(0);
    store_s();
    __syncthreads();

    for (int it = 0; it < kIters; it++) {
        if (it + 1 < kIters) load_g(it + 1);
        // compute on smem tile
#pragma unroll
        for (int ks = 0; ks < 2; ks++) {
            int kk = ks * 8;
            unsigned afr[2][4];
#pragma unroll
            for (int mt = 0; mt < 2; mt++) {
                int row = warp_m * 32 + mt * 16 + (lane >> 2);
                afr[mt][0] = As[kk + (lane & 3)][row];
                afr[mt][1] = As[kk + (lane & 3)][row + 8];
                afr[mt][2] = As[kk + (lane & 3) + 4][row];
                afr[mt][3] = As[kk + (lane & 3) + 4][row + 8];
            }
#pragma unroll
            for (int nt = 0; nt < 8; nt++) {
                int n = warp_n * 64 + nt * 8 + (lane >> 2);
                unsigned b0 = Bs[kk + (lane & 3)][n];
                unsigned b1 = Bs[kk + (lane & 3) + 4][n];
                mma_tf32(acc[0][nt], afr[0], b0, b1);
                mma_tf32(acc[1][nt], afr[1], b0, b1);
            }
        }
        __syncthreads();
        if (it + 1 < kIters) {
            store_s();
            __syncthreads();
        }
    }

    // epilogue: bias + store (float2 per c-pair)
#pragma unroll
    for (int mt = 0; mt < 2; mt++) {
#pragma unroll
        for (int half = 0; half < 2; half++) {
            int r = rowBase + warp_m * 32 + mt * 16 + (lane >> 2) + half * 8;
            if (r >= M) continue;
#pragma unroll
            for (int nt = 0; nt < 8; nt++) {
                int cc = colBase + warp_n * 64 + nt * 8 + 2 * (lane & 3);
                float2 v;
                v.x = acc[mt][nt][half * 2 + 0] + bias[cc];
                v.y = acc[mt][nt][half * 2 + 1] + bias[cc + 1];
                *(float2*)(C + (size_t)r * Nc + cc) = v;
            }
        }
    }
}

// ---------------- LayerNorm (+ optional GELU) ----------------
template <int DIM, bool ACT>
__global__ void ln_kernel(const float* __restrict__ in, const float* __restrict__ g,
                          const float* __restrict__ b, float* __restrict__ out) {
    int n = blockIdx.x, c = threadIdx.x;
    float v = in[n * DIM + c];
    __shared__ float sh[DIM];
    sh[c] = v;
    __syncthreads();
    for (int off = DIM / 2; off > 0; off >>= 1) {
        if (c < off) sh[c] += sh[c + off];
        __syncthreads();
    }
    float mean = sh[0] * (1.0f / DIM);
    __syncthreads();
    float d = v - mean;
    sh[c] = d * d;
    __syncthreads();
    for (int off = DIM / 2; off > 0; off >>= 1) {
        if (c < off) sh[c] += sh[c + off];
        __syncthreads();
    }
    float var = sh[0] * (1.0f / DIM);
    float y = d * rsqrtf(var + 1e-5f) * g[c] + b[c];
    if (ACT) y = gelu_f(y);
    out[n * DIM + c] = y;
}

// ---------------- GATv2 layer ----------------
__global__ void gat_kernel(const float* __restrict__ xl, const float* __restrict__ xr,
                           const float* __restrict__ att, const float* __restrict__ bias,
                           const float* __restrict__ lng, const float* __restrict__ lnb,
                           float* __restrict__ h) {
    int n = blockIdx.x;
    int c = threadIdx.x;
    float xr_c = xr[n * HID + c];
    float att_c = att[c];
    float m = -INFINITY, den = 0.0f, acc = 0.0f;
    int beg = g_rowptr[n], end = g_rowptr[n + 1];
    for (int j = beg; j <= end; j++) {
        int s = (j < end) ? g_csrc[j] : n;
        float xlc = xl[s * HID + c];
        float t = xlc + xr_c;
        t = (t > 0.0f) ? t : 0.2f * t;
        float p = t * att_c;
#pragma unroll
        for (int o = 16; o > 0; o >>= 1) p += __shfl_xor_sync(0xffffffffu, p, o);
        float mn = fmaxf(m, p);
        float sc = __expf(m - mn);
        float w = __expf(p - mn);
        acc = acc * sc + w * xlc;
        den = den * sc + w;
        m = mn;
    }
    float out = acc / (den + 1e-16f) + bias[c];
    __shared__ float sh[HID];
    sh[c] = out;
    __syncthreads();
    for (int off = HID / 2; off > 0; off >>= 1) {
        if (c < off) sh[c] += sh[c + off];
        __syncthreads();
    }
    float mean = sh[0] * (1.0f / HID);
    __syncthreads();
    float d = out - mean;
    sh[c] = d * d;
    __syncthreads();
    for (int off = HID / 2; off > 0; off >>= 1) {
        if (c < off) sh[c] += sh[c + off];
        __syncthreads();
    }
    float var = sh[0] * (1.0f / HID);
    float y = d * rsqrtf(var + 1e-5f) * lng[c] + lnb[c];
    h[n * HID + c] += gelu_f(y);
}

// ---------------- TransformerConv ----------------
__global__ void trans_kernel(const float* __restrict__ q, const float* __restrict__ k,
                             const float* __restrict__ v, const float* __restrict__ skip,
                             const float* __restrict__ lng, const float* __restrict__ lnb,
                             float* __restrict__ h) {
    int n = blockIdx.x;
    int c = threadIdx.x;
    const float scale = 0.17677669529663687f;
    float q_c = q[n * HID + c];
    float m = -INFINITY, den = 0.0f, acc = 0.0f;
    int beg = g_rowptr[n], end = g_rowptr[n + 1];
    for (int j = beg; j < end; j++) {
        int s = g_csrc[j];
        float kc = k[s * HID + c];
        float p = q_c * kc;
#pragma unroll
        for (int o = 16; o > 0; o >>= 1) p += __shfl_xor_sync(0xffffffffu, p, o);
        p *= scale;
        float vc = v[s * HID + c];
        float mn = fmaxf(m, p);
        float sc = __expf(m - mn);
        float w = __expf(p - mn);
        acc = acc * sc + w * vc;
        den = den * sc + w;
        m = mn;
    }
    float out = acc / (den + 1e-16f) + skip[n * HID + c];
    __shared__ float sh[HID];
    sh[c] = out;
    __syncthreads();
    for (int off = HID / 2; off > 0; off >>= 1) {
        if (c < off) sh[c] += sh[c + off];
        __syncthreads();
    }
    float mean = sh[0] * (1.0f / HID);
    __syncthreads();
    float d = out - mean;
    sh[c] = d * d;
    __syncthreads();
    for (int off = HID / 2; off > 0; off >>= 1) {
        if (c < off) sh[c] += sh[c + off];
        __syncthreads();
    }
    float var = sh[0] * (1.0f / HID);
    float y = d * rsqrtf(var + 1e-5f) * lng[c] + lnb[c];
    h[n * HID + c] += y;
}

// ---------------- pooling ----------------
__global__ void pool_kernel(const float* __restrict__ h, const int* __restrict__ batch) {
    int n = blockIdx.x, c = threadIdx.x;
    int g = batch[n];
    float v = h[n * HID + c];
    atomicAdd(&g_pool_sum[g * HID + c], v);
    atomicMaxFloat(&g_pool_max[g * HID + c], v);
    if (c == 0) atomicAdd(&g_cnt[g], 1.0f);
}

__global__ void finalize_kernel(int G) {
    int i = blockIdx.x * blockDim.x + threadIdx.x;
    if (i >= G * 2 * HID) return;
    int g = i / (2 * HID), c = i % (2 * HID);
    float v;
    if (c < HID) {
        v = g_pool_sum[g * HID + c] / fmaxf(g_cnt[g], 1.0f);
    } else {
        v = g_pool_max[g * HID + (c - HID)];
        if (!isfinite(v)) v = 0.0f;
    }
    g_ge[i] = v;
}

// ---------------- launch ----------------
static void run_gemm_f32(const float* A, const float* B, const float* bias, float* C,
                         int M, int K, int Nc) {
    dim3 grid((Nc + BN - 1) / BN, (M + BM - 1) / BM);
    gemm_bias_kernel<<<grid, 256>>>(A, B, bias, C, M, K, Nc);
}

static void run_gemm_tc(const float* A, const float* B, const float* bias, float* C,
                        int M, int K, int Nc) {
    dim3 grid(Nc / TBN, (M + TBM - 1) / TBM);
    gemm_tf32_kernel<<<grid, 256>>>(A, B, bias, C, M, K, Nc);
}

extern "C" void kernel_launch(void* const* d_in, const int* in_sizes, int n_in,
                              void* d_out, int out_size) {
    const float* x = (const float*)d_in[0];
    const int* ei = (const int*)d_in[1];
    const int* batch = (const int*)d_in[2];
    const float* in_W = (const float*)d_in[3];
    const float* in_b = (const float*)d_in[4];
    const float* in_ln_g = (const float*)d_in[5];
    const float* in_ln_b = (const float*)d_in[6];
    const float* gat_Wl = (const float*)d_in[7];
    const float* gat_bl = (const float*)d_in[8];
    const float* gat_Wr = (const float*)d_in[9];
    const float* gat_br = (const float*)d_in[10];
    const float* gat_att = (const float*)d_in[11];
    const float* gat_bias = (const float*)d_in[12];
    const float* gat_ln_g = (const float*)d_in[13];
    const float* gat_ln_b = (const float*)d_in[14];
    const float* tr_Wq = (const float*)d_in[15];
    const float* tr_bq = (const float*)d_in[16];
    const float* tr_Wk = (const float*)d_in[17];
    const float* tr_bk = (const float*)d_in[18];
    const float* tr_Wv = (const float*)d_in[19];
    const float* tr_bv = (const float*)d_in[20];
    const float* tr_Wskip = (const float*)d_in[21];
    const float* tr_bskip = (const float*)d_in[22];
    const float* tr_ln_g = (const float*)d_in[23];
    const float* tr_ln_b = (const float*)d_in[24];
    const float* out_W = (const float*)d_in[25];
    const float* out_b = (const float*)d_in[26];
    const float* out_ln_g = (const float*)d_in[27];
    const float* out_ln_b = (const float*)d_in[28];

    int N = in_sizes[0] / F_IN;
    int E = in_sizes[1] / 2;
    int G = out_size / (2 * HID);
    const int* src = ei;
    const int* dst = ei + E;

    float *hP, *aP, *bP, *cP, *tP, *geP;
    cudaGetSymbolAddress((void**)&hP, g_h);
    cudaGetSymbolAddress((void**)&aP, g_a);
    cudaGetSymbolAddress((void**)&bP, g_b);
    cudaGetSymbolAddress((void**)&cP, g_c);
    cudaGetSymbolAddress((void**)&tP, g_t);
    cudaGetSymbolAddress((void**)&geP, g_ge);

    int initN = (G * HID > N) ? G * HID : N;
    init_kernel<<<(initN + 255) / 256, 256>>>(N, G);

    // input embed (K=34, fp32): h = gelu(LN(x @ in_W + in_b))
    run_gemm_f32(x, in_W, in_b, tP, N, F_IN, HID);
    ln_kernel<HID, true><<<N, HID>>>(tP, in_ln_g, in_ln_b, hP);

    // build CSR by destination
    deg_kernel<<<(E + 255) / 256, 256>>>(dst, E);
    scan_kernel<<<1, 1024>>>(N);
    scatter_kernel<<<(E + 255) / 256, 256>>>(src, dst, E);

    // 5 GATv2 layers (tf32 tensor-core GEMMs)
    for (int l = 0; l < NLAYER; l++) {
        run_gemm_tc(hP, gat_Wl + (size_t)l * HID * HID, gat_bl + (size_t)l * HID, aP, N, HID, HID);
        run_gemm_tc(hP, gat_Wr + (size_t)l * HID * HID, gat_br + (size_t)l * HID, bP, N, HID, HID);
        gat_kernel<<<N, HID>>>(aP, bP, gat_att + (size_t)l * HID, gat_bias + (size_t)l * HID,
                               gat_ln_g + (size_t)l * HID, gat_ln_b + (size_t)l * HID, hP);
    }

    // TransformerConv (tf32)
    run_gemm_tc(hP, tr_Wq, tr_bq, aP, N, HID, HID);
    run_gemm_tc(hP, tr_Wk, tr_bk, bP, N, HID, HID);
    run_gemm_tc(hP, tr_Wv, tr_bv, cP, N, HID, HID);
    run_gemm_tc(hP, tr_Wskip, tr_bskip, tP, N, HID, HID);
    trans_kernel<<<N, HID>>>(aP, bP, cP, tP, tr_ln_g, tr_ln_b, hP);

    // pooling
    pool_kernel<<<N, HID>>>(hP, batch);
    finalize_kernel<<<(G * 2 * HID + 255) / 256, 256>>>(G);

    // output projection (fp32 for final accuracy) + LN + GELU
    run_gemm_f32(geP, out_W, out_b, bP, G, 2 * HID, 2 * HID);
    ln_kernel<2 * HID, true><<<G, 2 * HID>>>(bP, out_ln_g, out_ln_b, (float*)d_out);
}